// round 2
// baseline (speedup 1.0000x reference)
#include <cuda_runtime.h>
#include <cstdint>

#define N_BATCH 64
#define T_SEQ   2000
#define DQ      256
#define H_HEADS 8
#define NTOK    10
#define NJ      80            // H*NTOK
#define TILE    192
#define NTILES  11            // ceil(2000/192)
#define SCALE_LG 0.17677669529663687f  // 1/sqrt(32)

#define OUT_ELEMS (N_BATCH * T_SEQ * DQ)   // 32,768,000

// scratch (allocation-free rule: __device__ globals)
__device__ float g_Wqk[NJ * DQ];     // fused Wq ∘ tanh(embed)@Wk^T, pre-scaled
__device__ float g_vh[NTOK * DQ];    // tanh(embed)@Wv^T
__device__ int   g_idx_is64;

// ---------- packed f32x2 helpers (PTX-only, ptxas won't auto-fuse) ----------
__device__ __forceinline__ void fma2(unsigned long long& acc,
                                     unsigned long long a, unsigned long long b) {
    asm("fma.rn.f32x2 %0, %1, %2, %0;" : "+l"(acc) : "l"(a), "l"(b));
}
__device__ __forceinline__ float2 u2f2(unsigned long long v) {
    float2 r; asm("mov.b64 {%0, %1}, %2;" : "=f"(r.x), "=f"(r.y) : "l"(v)); return r;
}
__device__ __forceinline__ unsigned long long dupf(float a) {
    unsigned long long r; asm("mov.b64 %0, {%1, %1};" : "=l"(r) : "f"(a)); return r;
}

// =====================================================================
// Precompute: keys = tanh(embed); Wqk[j=h*10+k][i] = (1/sqrt32)*sum_d kh*Wq;
// vh[k][u] = keys@Wv^T. Also detect int64 vs int32 positional_indexes.
// blocks 0..79 -> one Wqk row each; block 80 -> vh + dtype detection.
// =====================================================================
__global__ void precompute_kernel(const float* __restrict__ embed,
                                  const float* __restrict__ Wq,
                                  const float* __restrict__ Wk,
                                  const float* __restrict__ Wv,
                                  const int*   __restrict__ pidx) {
    __shared__ float skeys[NTOK * 32];
    const int tid = threadIdx.x;
    for (int e = tid; e < NTOK * 32; e += 256)   // FIX: 320 elems > 256 threads
        skeys[e] = tanhf(embed[e]);
    __syncthreads();

    const int b = blockIdx.x;
    if (b < NJ) {
        const int h = b / NTOK, k = b % NTOK;
        __shared__ float skm[32];
        if (tid < 32) {
            const int u = h * 32 + tid;
            float s = 0.f;
            #pragma unroll
            for (int d = 0; d < 32; ++d) s += skeys[k * 32 + d] * Wk[u * 32 + d];
            skm[tid] = s;
        }
        __syncthreads();
        const int i = tid;  // 256 threads, one column each
        float s = 0.f;
        #pragma unroll
        for (int d = 0; d < 32; ++d) s += skm[d] * Wq[(h * 32 + d) * DQ + i];
        g_Wqk[b * DQ + i] = s * SCALE_LG;
    } else {
        for (int e = tid; e < NTOK * DQ; e += 256) {
            const int k = e >> 8, u = e & 255;
            float s = 0.f;
            #pragma unroll
            for (int d = 0; d < 32; ++d) s += skeys[k * 32 + d] * Wv[u * 32 + d];
            g_vh[k * DQ + u] = s;
        }
        if (tid == 0) {
            // int64 little-endian => every odd int32 word of the first 256
            // (sorted, < 2000) indexes is 0. False positive prob ~0.
            int is64 = 1;
            for (int t = 1; t < 512; t += 2)
                if (pidx[t] != 0) { is64 = 0; break; }
            g_idx_is64 = is64;
        }
    }
}

// =====================================================================
// Main fused kernel
// smem layout (dynamic, 194304 B total):
//   [0      , 81920)  sW   : Wqk as ull[80*128]
//   [81920  , 92160)  sVh  : vh  as ull[10*128]
//   [92160  , 193536) sX   : 2 x [192 rows x 33 ull (stride 66 floats)]
//                     sAttn: alias, float[192*81] (used after compute)
//   [193536 , 194304) sIdx : int[192]
// =====================================================================
#define OFF_V   81920
#define OFF_X   92160
#define OFF_IDX 193536
#define SMEM_BYTES 194304

__device__ __forceinline__ void stage_chunk(
    float* __restrict__ bx, const float* __restrict__ inputs,
    const float* __restrict__ ptab, const int* __restrict__ sIdx,
    int n, int t0, int c, int nrows, int tid)
{
    const int i4 = (tid & 15) << 2;   // 0..60
    const int r0 = tid >> 4;          // 0..15
    const int cb = c << 6;            // chunk base column
    #pragma unroll
    for (int m = 0; m < 12; ++m) {
        const int r = r0 + (m << 4);
        float4 v = make_float4(0.f, 0.f, 0.f, 0.f);
        if (r < nrows) {
            const float4 a = *(const float4*)(inputs + (size_t)(n * T_SEQ + t0 + r) * DQ + cb + i4);
            const float4 b = *(const float4*)(ptab   + (size_t)sIdx[r] * DQ + cb + i4);
            v.x = a.x + b.x; v.y = a.y + b.y; v.z = a.z + b.z; v.w = a.w + b.w;
        }
        float* d = bx + r * 66 + i4;  // 264B row stride: only 8B aligned -> float2 stores
        *(float2*)(d)     = make_float2(v.x, v.y);
        *(float2*)(d + 2) = make_float2(v.z, v.w);
    }
}

__global__ void __launch_bounds__(256, 1)
attn_kernel(const float* __restrict__ inputs, const int* __restrict__ pidx,
            const float* __restrict__ ptab, float* __restrict__ out,
            float* __restrict__ scores)
{
    extern __shared__ char smem[];
    unsigned long long* sW   = (unsigned long long*)(smem);
    unsigned long long* sVh  = (unsigned long long*)(smem + OFF_V);
    unsigned long long* sX   = (unsigned long long*)(smem + OFF_X);
    float*              sXf  = (float*)(smem + OFF_X);
    float*              sAttn= (float*)(smem + OFF_X);   // alias, used post-compute
    int*                sIdx = (int*)(smem + OFF_IDX);

    const int tid  = threadIdx.x;
    const int lane = tid & 31;
    const int warp = tid >> 5;         // head id
    const int t0   = blockIdx.x * TILE;
    const int n    = blockIdx.y;
    const int nrows = min(TILE, T_SEQ - t0);
    const int is64  = g_idx_is64;

    // ---- load Wqk + vh into smem (L2-resident), gather idx ----
    {
        const float4* wsrc = (const float4*)g_Wqk;
        float4* wdst = (float4*)sW;
        #pragma unroll
        for (int e = tid; e < NJ * DQ / 4; e += 256) wdst[e] = wsrc[e];
        const float4* vsrc = (const float4*)g_vh;
        float4* vdst = (float4*)sVh;
        #pragma unroll
        for (int e = tid; e < NTOK * DQ / 4; e += 256) vdst[e] = vsrc[e];
        if (tid < TILE) {
            int v = 0;
            if (tid < nrows) {
                const int pos = n * T_SEQ + t0 + tid;
                v = is64 ? pidx[2 * pos] : pidx[pos];
            }
            sIdx[tid] = v;
        }
    }
    __syncthreads();

    stage_chunk(sXf, inputs, ptab, sIdx, n, t0, 0, nrows, tid);
    __syncthreads();

    // ---- logits: acc[6 rows][10 toks] in packed f32x2 ----
    unsigned long long acc[6][10];
    #pragma unroll
    for (int jj = 0; jj < 6; ++jj)
        #pragma unroll
        for (int k = 0; k < NTOK; ++k) acc[jj][k] = 0ull;

    int p = 0;
    #pragma unroll 1
    for (int c = 0; c < 4; ++c) {
        if (c < 3) stage_chunk(sXf + (p ^ 1) * (TILE * 66), inputs, ptab, sIdx, n, t0, c + 1, nrows, tid);
        const unsigned long long* xb = sX + (size_t)p * (TILE * 33) + lane * 33;
        const unsigned long long* wb = sW + (warp * NTOK) * 128 + (c << 5);
        #pragma unroll 4
        for (int ii = 0; ii < 32; ++ii) {
            unsigned long long wv[NTOK];
            #pragma unroll
            for (int k = 0; k < NTOK; ++k) wv[k] = wb[k * 128 + ii];
            #pragma unroll
            for (int jj = 0; jj < 6; ++jj) {
                const unsigned long long xv = xb[jj * (32 * 33) + ii];
                #pragma unroll
                for (int k = 0; k < NTOK; ++k) fma2(acc[jj][k], xv, wv[k]);
            }
        }
        __syncthreads();
        p ^= 1;
    }

    // ---- softmax (in-register, 10 wide) + scores + smem attn ----
    #pragma unroll
    for (int jj = 0; jj < 6; ++jj) {
        float lg[NTOK];
        #pragma unroll
        for (int k = 0; k < NTOK; ++k) {
            const float2 f = u2f2(acc[jj][k]);
            lg[k] = f.x + f.y;            // SCALE folded into Wqk
        }
        float mx = lg[0];
        #pragma unroll
        for (int k = 1; k < NTOK; ++k) mx = fmaxf(mx, lg[k]);
        float s = 0.f;
        float at[NTOK];
        #pragma unroll
        for (int k = 0; k < NTOK; ++k) { at[k] = __expf(lg[k] - mx); s += at[k]; }
        const float inv = 1.0f / s;
        #pragma unroll
        for (int k = 0; k < NTOK; ++k) at[k] *= inv;

        const int r = lane + (jj << 5);
        #pragma unroll
        for (int k = 0; k < NTOK; ++k) sAttn[r * 81 + warp * NTOK + k] = at[k];
        if (r < nrows) {
            float* sp = scores + ((size_t)n * NJ + warp * NTOK) * T_SEQ + t0 + r;
            #pragma unroll
            for (int k = 0; k < NTOK; ++k) sp[k * T_SEQ] = at[k];
        }
    }
    __syncthreads();

    // ---- out = attn @ vh, coalesced float4 stores ----
    const int cg = tid & 63;          // column group (0..63) -> cols 4*cg..4*cg+3
    const int eh = cg >> 3;           // head owning these cols
    const int r0 = tid >> 6;          // 0..3
    for (int r = r0; r < nrows; r += 4) {
        const float* ar = sAttn + r * 81 + eh * NTOK;
        unsigned long long o0 = 0ull, o1 = 0ull;
        #pragma unroll
        for (int k = 0; k < NTOK; ++k) {
            const unsigned long long a2 = dupf(ar[k]);
            fma2(o0, a2, sVh[k * 128 + cg * 2]);
            fma2(o1, a2, sVh[k * 128 + cg * 2 + 1]);
        }
        const float2 f0 = u2f2(o0), f1 = u2f2(o1);
        *(float4*)(out + (size_t)(n * T_SEQ + t0 + r) * DQ + (cg << 2)) =
            make_float4(f0.x, f0.y, f1.x, f1.y);
    }
}

extern "C" void kernel_launch(void* const* d_in, const int* in_sizes, int n_in,
                              void* d_out, int out_size) {
    const float* inputs = (const float*)d_in[0];
    const int*   pidx   = (const int*)d_in[1];   // int32 OR little-endian int64 (runtime-detected)
    const float* embed  = (const float*)d_in[2];
    const float* Wq     = (const float*)d_in[3];
    const float* Wk     = (const float*)d_in[4];
    const float* Wv     = (const float*)d_in[5];
    const float* ptab   = (const float*)d_in[6];

    float* out    = (float*)d_out;
    float* scores = (float*)d_out + OUT_ELEMS;

    cudaFuncSetAttribute(attn_kernel, cudaFuncAttributeMaxDynamicSharedMemorySize, SMEM_BYTES);

    precompute_kernel<<<NJ + 1, 256>>>(embed, Wq, Wk, Wv, pidx);
    attn_kernel<<<dim3(NTILES, N_BATCH), 256, SMEM_BYTES>>>(inputs, pidx, ptab, out, scores);
}

// round 3
// speedup vs baseline: 1.2298x; 1.2298x over previous
#include <cuda_runtime.h>
#include <cstdint>

#define N_BATCH 64
#define T_SEQ   2000
#define DQ      256
#define H_HEADS 8
#define NTOK    10
#define NJ      80
#define TILE    128
#define NTILES  16            // ceil(2000/128)
#define THREADS 512
#define SCALE_LG 0.17677669529663687f  // 1/sqrt(32)

#define OUT_ELEMS (N_BATCH * T_SEQ * DQ)

// smem layout (bytes):
//   [0      , 81920 ) sW   : Wqk as ull[80*128]
//   [81920  , 92160 ) sVh  : vh  as ull[10*128]
//   [92160  , 161792) sX   : 2 x [128 rows x 34 ull]  (272B row stride)
//                     sAttn: alias float[128*81]
//   [161792 , 162304) sIdx : int[128]
#define OFF_V   81920
#define OFF_X   92160
#define OFF_IDX 161792
#define SMEM_BYTES 162304
#define XBUF_ULL (TILE * 34)   // 4352 ull per buffer

__device__ float g_Wqk[NJ * DQ];
__device__ float g_vh[NTOK * DQ];
__device__ int   g_idx_is64;

typedef unsigned long long ull;

__device__ __forceinline__ void fma2(ull& acc, ull a, ull b) {
    asm("fma.rn.f32x2 %0, %1, %2, %0;" : "+l"(acc) : "l"(a), "l"(b));
}
__device__ __forceinline__ float2 u2f2(ull v) {
    float2 r; asm("mov.b64 {%0, %1}, %2;" : "=f"(r.x), "=f"(r.y) : "l"(v)); return r;
}
__device__ __forceinline__ ull dupf(float a) {
    ull r; asm("mov.b64 %0, {%1, %1};" : "=l"(r) : "f"(a)); return r;
}

// =====================================================================
// Precompute (unchanged from R1 fix): Wqk, vh, int64-vs-int32 detection
// =====================================================================
__global__ void precompute_kernel(const float* __restrict__ embed,
                                  const float* __restrict__ Wq,
                                  const float* __restrict__ Wk,
                                  const float* __restrict__ Wv,
                                  const int*   __restrict__ pidx) {
    __shared__ float skeys[NTOK * 32];
    const int tid = threadIdx.x;
    for (int e = tid; e < NTOK * 32; e += 256)
        skeys[e] = tanhf(embed[e]);
    __syncthreads();

    const int b = blockIdx.x;
    if (b < NJ) {
        const int h = b / NTOK, k = b % NTOK;
        __shared__ float skm[32];
        if (tid < 32) {
            const int u = h * 32 + tid;
            float s = 0.f;
            #pragma unroll
            for (int d = 0; d < 32; ++d) s += skeys[k * 32 + d] * Wk[u * 32 + d];
            skm[tid] = s;
        }
        __syncthreads();
        const int i = tid;
        float s = 0.f;
        #pragma unroll
        for (int d = 0; d < 32; ++d) s += skm[d] * Wq[(h * 32 + d) * DQ + i];
        g_Wqk[b * DQ + i] = s * SCALE_LG;
    } else {
        for (int e = tid; e < NTOK * DQ; e += 256) {
            const int k = e >> 8, u = e & 255;
            float s = 0.f;
            #pragma unroll
            for (int d = 0; d < 32; ++d) s += skeys[k * 32 + d] * Wv[u * 32 + d];
            g_vh[k * DQ + u] = s;
        }
        if (tid == 0) {
            int is64 = 1;
            for (int t = 1; t < 512; t += 2)
                if (pidx[t] != 0) { is64 = 0; break; }
            g_idx_is64 = is64;
        }
    }
}

// =====================================================================
// Staging: chunk c (64 cols) of x = inputs + pos_table[idx] into sX.
// 512 threads: each does 4 guarded float4 pairs. 16B-aligned STS.128.
// =====================================================================
__device__ __forceinline__ void stage_chunk(
    float* __restrict__ bx, const float* __restrict__ inputs,
    const float* __restrict__ ptab, const int* __restrict__ sIdx,
    int n, int t0, int c, int nrows, int tid)
{
    const int i4 = (tid & 15) << 2;   // 0..60
    const int r0 = tid >> 4;          // 0..31
    const int cb = c << 6;
    #pragma unroll 2
    for (int m = 0; m < 4; ++m) {
        const int r = r0 + (m << 5);
        float4 v = make_float4(0.f, 0.f, 0.f, 0.f);
        if (r < nrows) {
            const float4 a = *(const float4*)(inputs + (size_t)(n * T_SEQ + t0 + r) * DQ + cb + i4);
            const float4 b = *(const float4*)(ptab   + (size_t)sIdx[r] * DQ + cb + i4);
            v.x = a.x + b.x; v.y = a.y + b.y; v.z = a.z + b.z; v.w = a.w + b.w;
        }
        *(float4*)(bx + r * 68 + i4) = v;   // 272B row stride, 16B aligned
    }
}

__global__ void __launch_bounds__(THREADS, 1)
attn_kernel(const float* __restrict__ inputs, const int* __restrict__ pidx,
            const float* __restrict__ ptab, float* __restrict__ out,
            float* __restrict__ scores)
{
    extern __shared__ char smem[];
    ull*   sW    = (ull*)(smem);
    ull*   sVh   = (ull*)(smem + OFF_V);
    ull*   sX    = (ull*)(smem + OFF_X);
    float* sXf   = (float*)(smem + OFF_X);
    float* sAttn = (float*)(smem + OFF_X);   // alias, used post-compute
    int*   sIdx  = (int*)(smem + OFF_IDX);

    const int tid  = threadIdx.x;
    const int lane = tid & 31;
    const int warp = tid >> 5;        // 0..15
    const int head = warp >> 1;       // 0..7
    const int half = warp & 1;        // row half within tile
    const int t0   = blockIdx.x * TILE;
    const int n    = blockIdx.y;
    const int nrows = min(TILE, T_SEQ - t0);
    const int is64  = g_idx_is64;

    // ---- cooperative loads: Wqk (80KB), vh (10KB), indexes ----
    {
        const float4* wsrc = (const float4*)g_Wqk;
        float4* wdst = (float4*)sW;
        #pragma unroll
        for (int e = tid; e < NJ * DQ / 4; e += THREADS) wdst[e] = wsrc[e];
        const float4* vsrc = (const float4*)g_vh;
        float4* vdst = (float4*)sVh;
        for (int e = tid; e < NTOK * DQ / 4; e += THREADS) vdst[e] = vsrc[e];
        if (tid < TILE) {
            int v = 0;
            if (tid < nrows) {
                const int pos = n * T_SEQ + t0 + tid;
                v = is64 ? pidx[2 * pos] : pidx[pos];
            }
            sIdx[tid] = v;
        }
    }
    __syncthreads();

    stage_chunk(sXf, inputs, ptab, sIdx, n, t0, 0, nrows, tid);
    __syncthreads();

    // ---- logits: acc[2 rows][10 toks], packed f32x2 ----
    ull acc[2][NTOK];
    #pragma unroll
    for (int jj = 0; jj < 2; ++jj)
        #pragma unroll
        for (int k = 0; k < NTOK; ++k) acc[jj][k] = 0ull;

    int p = 0;
    #pragma unroll 1
    for (int c = 0; c < 4; ++c) {
        if (c < 3) stage_chunk(sXf + (p ^ 1) * (XBUF_ULL * 2), inputs, ptab, sIdx, n, t0, c + 1, nrows, tid);
        const ull* xb = sX + p * XBUF_ULL + (half * 64 + lane) * 34;
        const ull* wb = sW + (head * NTOK) * 128 + (c << 5);
        #pragma unroll 4
        for (int ii2 = 0; ii2 < 16; ++ii2) {
            const ulonglong2 xv0 = *(const ulonglong2*)(xb + 2 * ii2);
            const ulonglong2 xv1 = *(const ulonglong2*)(xb + 32 * 34 + 2 * ii2);
            #pragma unroll
            for (int kb = 0; kb < NTOK; kb += 5) {
                ulonglong2 wv[5];
                #pragma unroll
                for (int kk = 0; kk < 5; ++kk)
                    wv[kk] = *(const ulonglong2*)(wb + (kb + kk) * 128 + 2 * ii2);
                #pragma unroll
                for (int kk = 0; kk < 5; ++kk) {
                    fma2(acc[0][kb + kk], xv0.x, wv[kk].x);
                    fma2(acc[0][kb + kk], xv0.y, wv[kk].y);
                    fma2(acc[1][kb + kk], xv1.x, wv[kk].x);
                    fma2(acc[1][kb + kk], xv1.y, wv[kk].y);
                }
            }
        }
        __syncthreads();
        p ^= 1;
    }

    // ---- softmax (10-wide, in-register) + scores + attn->smem ----
    #pragma unroll
    for (int jj = 0; jj < 2; ++jj) {
        float lg[NTOK];
        #pragma unroll
        for (int k = 0; k < NTOK; ++k) {
            const float2 f = u2f2(acc[jj][k]);
            lg[k] = f.x + f.y;
        }
        float mx = lg[0];
        #pragma unroll
        for (int k = 1; k < NTOK; ++k) mx = fmaxf(mx, lg[k]);
        float s = 0.f;
        float at[NTOK];
        #pragma unroll
        for (int k = 0; k < NTOK; ++k) { at[k] = __expf(lg[k] - mx); s += at[k]; }
        const float inv = 1.0f / s;
        #pragma unroll
        for (int k = 0; k < NTOK; ++k) at[k] *= inv;

        const int r = half * 64 + (jj << 5) + lane;
        #pragma unroll
        for (int k = 0; k < NTOK; ++k) sAttn[r * 81 + head * NTOK + k] = at[k];
        if (r < nrows) {
            float* sp = scores + ((size_t)n * NJ + head * NTOK) * T_SEQ + t0 + r;
            #pragma unroll
            for (int k = 0; k < NTOK; ++k) sp[k * T_SEQ] = at[k];
        }
    }
    __syncthreads();

    // ---- out = attn @ vh, float4 coalesced stores ----
    const int cg = tid & 63;          // cols 4*cg..4*cg+3
    const int eh = cg >> 3;           // owning head
    const int rr0 = tid >> 6;         // 0..7
    for (int r = rr0; r < nrows; r += 8) {
        const float* ar = sAttn + r * 81 + eh * NTOK;
        ull o0 = 0ull, o1 = 0ull;
        #pragma unroll
        for (int k = 0; k < NTOK; ++k) {
            const ull a2 = dupf(ar[k]);
            const ulonglong2 vv = *(const ulonglong2*)(sVh + k * 128 + cg * 2);
            fma2(o0, a2, vv.x);
            fma2(o1, a2, vv.y);
        }
        const float2 f0 = u2f2(o0), f1 = u2f2(o1);
        *(float4*)(out + (size_t)(n * T_SEQ + t0 + r) * DQ + (cg << 2)) =
            make_float4(f0.x, f0.y, f1.x, f1.y);
    }
}

extern "C" void kernel_launch(void* const* d_in, const int* in_sizes, int n_in,
                              void* d_out, int out_size) {
    const float* inputs = (const float*)d_in[0];
    const int*   pidx   = (const int*)d_in[1];
    const float* embed  = (const float*)d_in[2];
    const float* Wq     = (const float*)d_in[3];
    const float* Wk     = (const float*)d_in[4];
    const float* Wv     = (const float*)d_in[5];
    const float* ptab   = (const float*)d_in[6];

    float* out    = (float*)d_out;
    float* scores = (float*)d_out + OUT_ELEMS;

    cudaFuncSetAttribute(attn_kernel, cudaFuncAttributeMaxDynamicSharedMemorySize, SMEM_BYTES);

    precompute_kernel<<<NJ + 1, 256>>>(embed, Wq, Wk, Wv, pidx);
    attn_kernel<<<dim3(NTILES, N_BATCH), THREADS, SMEM_BYTES>>>(inputs, pidx, ptab, out, scores);
}